// round 14
// baseline (speedup 1.0000x reference)
#include <cuda_runtime.h>
#include <cuda_bf16.h>
#include <cstdint>
#include <cstddef>

// ---------------- problem constants ----------------
#define NAG 64           // B*A
#define DIN 360          // logical dim
#define DD  (DIN*DIN)
#define MODE_LEN 60
#define DP  384          // padded dim (3 x 128)
#define DP2 (DP*DP)

// ---------------- scratch: bf16 hi/lo pairs ----------------
__device__ __align__(128) __nv_bfloat16 g_Sh [(size_t)NAG*DP2];
__device__ __align__(128) __nv_bfloat16 g_Sl [(size_t)NAG*DP2];
__device__ __align__(128) __nv_bfloat16 g_XAh[(size_t)NAG*DP2];
__device__ __align__(128) __nv_bfloat16 g_XAl[(size_t)NAG*DP2];
__device__ __align__(128) __nv_bfloat16 g_XBh[(size_t)NAG*DP2];
__device__ __align__(128) __nv_bfloat16 g_XBl[(size_t)NAG*DP2];
__device__ __align__(128) __nv_bfloat16 g_Yh [(size_t)NAG*DP2];
__device__ __align__(128) __nv_bfloat16 g_Yl [(size_t)NAG*DP2];
__device__ float g_rowsum[NAG * DIN];
__device__ float g_r[NAG];
__device__ int   g_upd[NAG];
__device__ int   g_initnew[NAG];
__device__ int   g_initout[NAG];

__device__ __forceinline__ __nv_bfloat16* selH(int s) {
    switch (s) {
        case 0:  return g_Sh;
        case 1:  return g_XAh;
        case 2:  return g_XBh;
        default: return g_Yh;
    }
}
__device__ __forceinline__ __nv_bfloat16* selL(int s) {
    switch (s) {
        case 0:  return g_Sl;
        case 1:  return g_XAl;
        case 2:  return g_XBl;
        default: return g_Yl;
    }
}

__device__ __forceinline__ int srcIdx(int g) {
    int l = g % MODE_LEN;
    return (l < MODE_LEN - 2) ? (g + 2) : g;
}

// ---------------- small helpers ----------------
__device__ __forceinline__ uint32_t smem_u32(const void* p) {
    uint32_t a;
    asm("{ .reg .u64 t; cvta.to.shared.u64 t, %1; cvt.u32.u64 %0, t; }"
        : "=r"(a) : "l"(p));
    return a;
}
__device__ __forceinline__ uint32_t pack_bf2(float x, float y) {
    __nv_bfloat162 t = __floats2bfloat162_rn(x, y);
    return *reinterpret_cast<uint32_t*>(&t);
}
__device__ __forceinline__ float2 bf2f(uint32_t u) {
    __nv_bfloat162 t = *reinterpret_cast<__nv_bfloat162*>(&u);
    return make_float2(__bfloat162float(t.x), __bfloat162float(t.y));
}
__device__ __forceinline__ void split2(float a, float b, uint32_t& h, uint32_t& l) {
    __nv_bfloat16 ah = __float2bfloat16_rn(a), bh = __float2bfloat16_rn(b);
    float ar = a - __bfloat162float(ah), br = b - __bfloat162float(bh);
    __nv_bfloat162 t; t.x = ah; t.y = bh;
    h = *reinterpret_cast<uint32_t*>(&t);
    l = pack_bf2(ar, br);
}

// ---------------- flag dtype sniffing (validated round 2) ----------------
__device__ int detect_mode(const unsigned char* p) {
    int n_off = 0, n_3f = 0;
    for (int t = 0; t < 64; t++) {
        unsigned char b = p[t];
        if ((t & 3) && b) n_off++;
        if (((t & 3) == 3) && b == 0x3F) n_3f++;
    }
    if (n_off == 0) return 1;
    if (n_3f > 0)  return 2;
    return 0;
}
__device__ __forceinline__ bool read_flag(const void* p, int t, int mode) {
    if (mode == 1) return ((const int*)p)[t] != 0;
    if (mode == 2) return ((const float*)p)[t] != 0.0f;
    return ((const unsigned char*)p)[t] != 0;
}

__global__ void prep_flags(const float* __restrict__ rs,
                           const void* __restrict__ ini,
                           const void* __restrict__ sel) {
    __shared__ int mode_i, mode_s;
    if (threadIdx.x == 0) {
        mode_i = detect_mode((const unsigned char*)ini);
        mode_s = detect_mode((const unsigned char*)sel);
    }
    __syncthreads();
    int t = threadIdx.x;
    if (t >= NAG) return;
    float r = rs[t] + 1.0f;
    bool i8 = read_flag(ini, t, mode_i);
    bool s8 = read_flag(sel, t, mode_s);
    g_r[t] = r;
    g_upd[t] = (s8 && i8);
    g_initnew[t] = (s8 && !i8);
    g_initout[t] = (s8 || i8);
}

// ---------------- S = A P A^T + (1+r)I -> split bf16 + fused Gershgorin ---
__global__ void build_S(const float* __restrict__ cov) {
    int a = blockIdx.y;
    if (!g_upd[a]) return;
    int warp = threadIdx.x >> 5, lane = threadIdx.x & 31;
    int i = blockIdx.x * 8 + warp;
    float r = g_r[a];
    size_t off = (size_t)a * DP2 + (size_t)i * DP + lane * 12;
    if (i < DIN) {
        const float* row = cov + (size_t)a * DD + (size_t)srcIdx(i) * DIN;
        float asum = 0.0f;
        #pragma unroll
        for (int g = 0; g < 3; g++) {
            float v[4];
            #pragma unroll
            for (int q = 0; q < 4; q++) {
                int j = lane * 12 + g * 4 + q;
                float x = 0.0f;
                if (j < DIN) {
                    x = row[srcIdx(j)];
                    if (j == i) x += 1.0f + r;
                }
                v[q] = x;
                asum += fabsf(x);
            }
            uint32_t h0, l0, h1, l1;
            split2(v[0], v[1], h0, l0);
            split2(v[2], v[3], h1, l1);
            *(uint2*)(g_Sh + off + g * 4) = make_uint2(h0, h1);
            *(uint2*)(g_Sl + off + g * 4) = make_uint2(l0, l1);
        }
        #pragma unroll
        for (int o = 16; o; o >>= 1) asum += __shfl_xor_sync(0xffffffffu, asum, o);
        if (lane == 0) g_rowsum[a * DIN + i] = asum;
    } else {
        #pragma unroll
        for (int g = 0; g < 3; g++) {
            float v[4];
            #pragma unroll
            for (int q = 0; q < 4; q++)
                v[q] = (lane * 12 + g * 4 + q == i) ? 1.0f : 0.0f;
            uint32_t h0, l0, h1, l1;
            split2(v[0], v[1], h0, l0);
            split2(v[2], v[3], h1, l1);
            *(uint2*)(g_Sh + off + g * 4) = make_uint2(h0, h1);
            *(uint2*)(g_Sl + off + g * 4) = make_uint2(l0, l1);
        }
    }
}

// X0 = 2c I - c^2 S -> split bf16 into XA. Gershgorin max fused per block.
__global__ void fill_X(void) {
    int a = blockIdx.y;
    if (!g_upd[a]) return;
    int tid = threadIdx.x;
    __shared__ float wm8[8];
    __shared__ float sc;
    float m = 0.0f;
    for (int i = tid; i < DIN; i += 256) m = fmaxf(m, g_rowsum[a * DIN + i]);
    #pragma unroll
    for (int o = 16; o; o >>= 1) m = fmaxf(m, __shfl_xor_sync(0xffffffffu, m, o));
    if ((tid & 31) == 0) wm8[tid >> 5] = m;
    __syncthreads();
    if (tid == 0) {
        float G = 0.0f;
        #pragma unroll
        for (int w = 0; w < 8; w++) G = fmaxf(G, wm8[w]);
        sc = 2.0f / (1.0f + g_r[a] + G * 1.0002f);
    }
    __syncthreads();
    float c = sc;

    int e4 = blockIdx.x * 256 + tid;   // < DP2/4 = 36864
    int i = e4 / 96;
    int jj = (e4 - i * 96) * 4;
    size_t off = (size_t)a * DP2 + (size_t)i * DP + jj;
    uint2 sh = *(const uint2*)(g_Sh + off);
    uint2 sl = *(const uint2*)(g_Sl + off);
    float2 h0 = bf2f(sh.x), h1 = bf2f(sh.y);
    float2 l0 = bf2f(sl.x), l1 = bf2f(sl.y);
    float s0 = h0.x + l0.x, s1 = h0.y + l0.y, s2 = h1.x + l1.x, s3 = h1.y + l1.y;
    float c2 = c * c;
    float v0 = ((i == jj)     ? 2.0f * c : 0.0f) - c2 * s0;
    float v1 = ((i == jj + 1) ? 2.0f * c : 0.0f) - c2 * s1;
    float v2 = ((i == jj + 2) ? 2.0f * c : 0.0f) - c2 * s2;
    float v3 = ((i == jj + 3) ? 2.0f * c : 0.0f) - c2 * s3;
    uint32_t a0, b0, a1, b1;
    split2(v0, v1, a0, b0);
    split2(v2, v3, a1, b1);
    *(uint2*)(g_XAh + off) = make_uint2(a0, a1);
    *(uint2*)(g_XAl + off) = make_uint2(b0, b1);
}

// ================= pipelined mma.sync bf16 GEMM (symmetric tiles) =====
// k-chunk 64, LDT=72 halves (144B rows: conflict-free ldmatrix, 6 chunks).
#define LDT 72
#define PA_E (128 * LDT)     // 9216 elems = 18432 B
#define PA_B (PA_E * 2)

__device__ __forceinline__ void ldm_x4(uint32_t* r, uint32_t addr) {
    asm volatile("ldmatrix.sync.aligned.m8n8.x4.shared.b16 {%0,%1,%2,%3}, [%4];"
                 : "=r"(r[0]), "=r"(r[1]), "=r"(r[2]), "=r"(r[3]) : "r"(addr));
}
__device__ __forceinline__ void mma_bf16(float* d, const uint32_t* a, const uint32_t* b) {
    asm volatile(
        "mma.sync.aligned.m16n8k16.row.col.f32.bf16.bf16.f32 "
        "{%0,%1,%2,%3}, {%4,%5,%6,%7}, {%8,%9}, {%0,%1,%2,%3};"
        : "+f"(d[0]), "+f"(d[1]), "+f"(d[2]), "+f"(d[3])
        : "r"(a[0]), "r"(a[1]), "r"(a[2]), "r"(a[3]), "r"(b[0]), "r"(b[1]));
}

// stage one ROWSx64 bf16 panel (128B rows = 8 x 16B) global -> SMEM
template<int ROWS>
__device__ __forceinline__ void stageP(const __nv_bfloat16* __restrict__ g,
                                       int row0, int k0, uint32_t dst, int tid) {
    const __nv_bfloat16* src0 = g + (size_t)row0 * DP + k0;
    #pragma unroll
    for (int i = 0; i < ROWS / 32; i++) {
        int id = i * 256 + tid;
        int row = id >> 3, part = id & 7;
        uint32_t d = dst + (uint32_t)(row * LDT + part * 8) * 2;
        const void* s = src0 + (size_t)row * DP + part * 8;
        asm volatile("cp.async.cg.shared.global [%0], [%1], 16;"
                     :: "r"(d), "l"(s));
    }
}

// SPLIT=0: hi*hi, double-buffered pipeline.
// SPLIT=1: 4 panels staged once per chunk into ONE buffer (3 CTAs/SM), 3 passes.
// MODE 0: C = A*B ; MODE 1: C = 2X - A*B ; MODE 3: C = A*B - I ;
// MODE 6: C = X - A*B (quadratic finish).
// XLO: read X lo plane. WRITELO: write C lo plane.
// FINAL: also write r*I - r^2*C to outp (fp32). MINC: min CTAs/SM.
template<int SPLIT, int MODE, int XLO, int WRITELO, int FINAL, int NT, int MINC>
__global__ __launch_bounds__(256, MINC)
void gemm_mma(int sA, int sB, int sX, int sC, float* outp) {
    int z = blockIdx.z;
    if (!g_upd[z]) return;

    const int bim[12] = {0, 0, 0, 0, 0, 0, 1, 1, 1, 1, 2, 2};
    const int bjm[12] = {0, 1, 2, 3, 4, 5, 2, 3, 4, 5, 4, 5};
    int bi = bim[blockIdx.x], bj = bjm[blockIdx.x];
    int m0 = bi * 128, n0 = bj * NT;
    bool offd = ((bj >> 1) != bi);

    constexpr int PB_E = NT * LDT;
    constexpr int PB_B = PB_E * 2;
    constexpr int MT = 2;              // NT = 64
    constexpr int LDCn = 65;
    constexpr int STAGE_E = (SPLIT ? 2 : 1) * (PA_E + PB_E);
    constexpr uint32_t STAGE_B = STAGE_E * 2;

    size_t zo = (size_t)z * DP2;
    const __nv_bfloat16* AH = selH(sA) + zo;
    const __nv_bfloat16* AL = selL(sA) + zo;
    const __nv_bfloat16* BH = selH(sB) + zo;
    const __nv_bfloat16* BL = selL(sB) + zo;
    const __nv_bfloat16* XH = selH(sX) + zo;
    const __nv_bfloat16* XL = selL(sX) + zo;
    __nv_bfloat16* CH = selH(sC) + zo;
    __nv_bfloat16* CL = selL(sC) + zo;

    extern __shared__ __align__(16) __nv_bfloat16 sm[];
    float* Cs = reinterpret_cast<float*>(sm);
    uint32_t sbase = smem_u32(sm);

    int tid = threadIdx.x, wid = tid >> 5, lane = tid & 31;
    int wm = (wid & 3) * 32;
    int wn = (wid >> 2) * 32;

    float acc[MT][4][4];
    #pragma unroll
    for (int i = 0; i < MT; i++)
        #pragma unroll
        for (int j = 0; j < 4; j++)
            #pragma unroll
            for (int q = 0; q < 4; q++) acc[i][j][q] = 0.0f;

    int lt = lane >> 3, lr = lane & 7;
    int a_row = (lt & 1) * 8 + lr;
    int a_col = (lt >> 1) * 8;
    int b_row = (lt >> 1) * 8 + lr;
    int b_col = (lt & 1) * 8;

    auto do_stage = [&](int kc, int b) {
        uint32_t base = sbase + (uint32_t)b * STAGE_B;
        int k0 = kc * 64;
        stageP<128>(AH, m0, k0, base, tid);
        stageP<NT>(BH, n0, k0, base + PA_B, tid);
        if (SPLIT) {
            stageP<128>(AL, m0, k0, base + PA_B + PB_B, tid);
            stageP<NT>(BL, n0, k0, base + 2 * PA_B + PB_B, tid);
        }
        asm volatile("cp.async.commit_group;");
    };

    auto do_compute = [&](int cur) {
        const __nv_bfloat16* At  = sm + (size_t)cur * STAGE_E;
        const __nv_bfloat16* Bt  = At + PA_E;
        const __nv_bfloat16* Alt = Bt + PB_E;
        const __nv_bfloat16* Blt = Alt + PA_E;

        #pragma unroll
        for (int ks = 0; ks < 4; ks++) {
            int kk = ks * 16;
            uint32_t ah[MT][4], bh[4][2];
            #pragma unroll
            for (int mt = 0; mt < MT; mt++)
                ldm_x4(ah[mt], smem_u32(&At[(wm + mt * 16 + a_row) * LDT + kk + a_col]));
            #pragma unroll
            for (int np = 0; np < 2; np++) {
                uint32_t r[4];
                ldm_x4(r, smem_u32(&Bt[(wn + np * 16 + b_row) * LDT + kk + b_col]));
                bh[np * 2][0] = r[0]; bh[np * 2][1] = r[1];
                bh[np * 2 + 1][0] = r[2]; bh[np * 2 + 1][1] = r[3];
            }
            #pragma unroll
            for (int mt = 0; mt < MT; mt++)
                #pragma unroll
                for (int nt = 0; nt < 4; nt++)
                    mma_bf16(acc[mt][nt], ah[mt], bh[nt]);

            if (SPLIT) {
                uint32_t bl[4][2];
                #pragma unroll
                for (int np = 0; np < 2; np++) {
                    uint32_t r[4];
                    ldm_x4(r, smem_u32(&Blt[(wn + np * 16 + b_row) * LDT + kk + b_col]));
                    bl[np * 2][0] = r[0]; bl[np * 2][1] = r[1];
                    bl[np * 2 + 1][0] = r[2]; bl[np * 2 + 1][1] = r[3];
                }
                #pragma unroll
                for (int mt = 0; mt < MT; mt++)
                    #pragma unroll
                    for (int nt = 0; nt < 4; nt++)
                        mma_bf16(acc[mt][nt], ah[mt], bl[nt]);
                uint32_t al[MT][4];
                #pragma unroll
                for (int mt = 0; mt < MT; mt++)
                    ldm_x4(al[mt], smem_u32(&Alt[(wm + mt * 16 + a_row) * LDT + kk + a_col]));
                #pragma unroll
                for (int mt = 0; mt < MT; mt++)
                    #pragma unroll
                    for (int nt = 0; nt < 4; nt++)
                        mma_bf16(acc[mt][nt], al[mt], bh[nt]);
            }
        }
    };

    if (SPLIT) {
        // single-buffer: stage -> wait -> compute -> fence; 3 CTAs/SM cover gaps
        for (int kc = 0; kc < 6; kc++) {
            do_stage(kc, 0);
            asm volatile("cp.async.wait_group 0;");
            __syncthreads();
            do_compute(0);
            __syncthreads();   // buffer reuse fence
        }
    } else {
        do_stage(0, 0);
        for (int kc = 0; kc < 6; kc++) {
            asm volatile("cp.async.wait_group 0;");
            __syncthreads();   // certifies compute(kc-1) done; buffer kc+1 free
            if (kc + 1 < 6) do_stage(kc + 1, (kc + 1) & 1);
            do_compute(kc & 1);
        }
        __syncthreads();   // protect Cs reuse of staging smem
    }

    // ---- epilogue ----
    float r = g_r[z];
    float rr = -r * r;
    #pragma unroll
    for (int mt = 0; mt < MT; mt++) {
        int rl0 = wm + mt * 16 + (lane >> 2);
        #pragma unroll
        for (int nt = 0; nt < 4; nt++) {
            int cl0 = wn + nt * 8 + 2 * (lane & 3);
            float v00 = acc[mt][nt][0], v01 = acc[mt][nt][1];
            float v10 = acc[mt][nt][2], v11 = acc[mt][nt][3];
            size_t g0 = (size_t)(m0 + rl0) * DP + n0 + cl0;
            size_t g1 = g0 + 8 * DP;
            int gi0 = m0 + rl0, gj = n0 + cl0;
            if (MODE == 1 || MODE == 6) {
                float2 xh0 = bf2f(*(const uint32_t*)(XH + g0));
                float2 xh1 = bf2f(*(const uint32_t*)(XH + g1));
                float x00 = xh0.x, x01 = xh0.y, x10 = xh1.x, x11 = xh1.y;
                if (XLO) {
                    float2 xl0 = bf2f(*(const uint32_t*)(XL + g0));
                    float2 xl1 = bf2f(*(const uint32_t*)(XL + g1));
                    x00 += xl0.x; x01 += xl0.y; x10 += xl1.x; x11 += xl1.y;
                }
                if (MODE == 1) {
                    v00 = 2.0f * x00 - v00; v01 = 2.0f * x01 - v01;
                    v10 = 2.0f * x10 - v10; v11 = 2.0f * x11 - v11;
                } else {                 // MODE 6: C = X - A*B
                    v00 = x00 - v00; v01 = x01 - v01;
                    v10 = x10 - v10; v11 = x11 - v11;
                }
            }
            if (MODE == 3) {   // C = A*B - I
                if (gi0 == gj)     v00 -= 1.0f;
                if (gi0 == gj + 1) v01 -= 1.0f;
                if (gi0 + 8 == gj)     v10 -= 1.0f;
                if (gi0 + 8 == gj + 1) v11 -= 1.0f;
            }
            uint32_t h, l;
            split2(v00, v01, h, l);
            *(uint32_t*)(CH + g0) = h;
            if (WRITELO) *(uint32_t*)(CL + g0) = l;
            split2(v10, v11, h, l);
            *(uint32_t*)(CH + g1) = h;
            if (WRITELO) *(uint32_t*)(CL + g1) = l;
            if (FINAL) {
                if (gj < DIN) {
                    if (gi0 < DIN) {
                        float2 o;
                        o.x = rr * v00 + ((gi0 == gj) ? r : 0.0f);
                        o.y = rr * v01 + ((gi0 == gj + 1) ? r : 0.0f);
                        *(float2*)(outp + (size_t)z * DD + (size_t)gi0 * DIN + gj) = o;
                    }
                    int gi1 = gi0 + 8;
                    if (gi1 < DIN) {
                        float2 o;
                        o.x = rr * v10 + ((gi1 == gj) ? r : 0.0f);
                        o.y = rr * v11 + ((gi1 == gj + 1) ? r : 0.0f);
                        *(float2*)(outp + (size_t)z * DD + (size_t)gi1 * DIN + gj) = o;
                    }
                }
            }
            if (offd) {
                Cs[rl0 * LDCn + cl0] = v00;
                Cs[rl0 * LDCn + cl0 + 1] = v01;
                Cs[(rl0 + 8) * LDCn + cl0] = v10;
                Cs[(rl0 + 8) * LDCn + cl0 + 1] = v11;
            }
        }
    }

    if (offd) {
        __syncthreads();
        #pragma unroll
        for (int it = 0; it < NT / 4; it++) {
            int p = it * 256 + tid;
            int cc = p >> 6, mp = (p & 63) * 2;
            float v0 = Cs[mp * LDCn + cc];
            float v1 = Cs[(mp + 1) * LDCn + cc];
            int gi = n0 + cc, gj = m0 + mp;
            size_t g = (size_t)gi * DP + gj;
            uint32_t h, l;
            split2(v0, v1, h, l);
            *(uint32_t*)(CH + g) = h;
            if (WRITELO) *(uint32_t*)(CL + g) = l;
            if (FINAL) {
                if (gi < DIN && gj < DIN) {
                    float2 o;
                    o.x = rr * v0;
                    o.y = rr * v1;
                    *(float2*)(outp + (size_t)z * DD + (size_t)gi * DIN + gj) = o;
                }
            }
        }
    }
}

// ---------------- outputs ----------------
#define OUT_MEAN 0
#define OUT_COV  (NAG * DIN)
#define OUT_INIT (NAG * DIN + NAG * DD)

__global__ void finalize_cov_rest(const float* __restrict__ cov,
                                  float* __restrict__ out) {
    int a = blockIdx.y;
    if (g_upd[a]) return;
    int e4 = blockIdx.x * blockDim.x + threadIdx.x;
    if (e4 >= DD / 4) return;
    int i = e4 / 90;
    int jj = (e4 - i * 90) * 4;
    float4 o = *(const float4*)(cov + (size_t)a * DD + (size_t)i * DIN + jj);
    if (g_initnew[a]) {
        if (i >= jj && i < jj + 4) (&o.x)[i - jj] += g_r[a];
    }
    *(float4*)(out + OUT_COV + (size_t)a * DD + (size_t)i * DIN + jj) = o;
}

__global__ void finalize_mean(const float* __restrict__ mean_in,
                              const float* __restrict__ obs,
                              float* __restrict__ out, int sinv) {
    int a = blockIdx.x;
    int tid = threadIdx.x;
    __shared__ float v[DIN];

    if (tid == 0) out[OUT_INIT + a] = g_initout[a] ? 1.0f : 0.0f;

    const float* m = mean_in + (size_t)a * DIN;
    const float* o = obs + (size_t)a * DIN;
    float* om = out + OUT_MEAN + (size_t)a * DIN;

    if (g_initnew[a]) {
        for (int i = tid; i < DIN; i += blockDim.x) om[i] = o[i];
    } else if (g_upd[a]) {
        float r = g_r[a];
        const __nv_bfloat16* Xh = selH(sinv) + (size_t)a * DP2;
        const __nv_bfloat16* Xl = selL(sinv) + (size_t)a * DP2;
        for (int j = tid; j < DIN; j += blockDim.x) v[j] = o[j] - m[srcIdx(j)];
        __syncthreads();
        int warp = tid >> 5, lane = tid & 31;
        for (int i = warp; i < DIN; i += 8) {
            float s = 0.0f;
            size_t row = (size_t)i * DP;
            for (int j = lane; j < DIN; j += 32)
                s += (__bfloat162float(Xh[row + j]) + __bfloat162float(Xl[row + j])) * v[j];
            #pragma unroll
            for (int off = 16; off; off >>= 1) s += __shfl_xor_sync(0xffffffffu, s, off);
            if (lane == 0) om[i] = o[i] - r * s;
        }
    } else {
        for (int i = tid; i < DIN; i += blockDim.x) om[i] = m[i];
    }
}

// ---------------- launch ----------------
extern "C" void kernel_launch(void* const* d_in, const int* in_sizes, int n_in,
                              void* d_out, int out_size) {
    const float* mean = (const float*)d_in[0];
    const float* cov  = (const float*)d_in[1];
    const float* obs  = (const float*)d_in[2];
    const float* rs   = (const float*)d_in[3];
    const void*  ini  = d_in[4];
    const void*  sel  = d_in[5];
    float* out = (float*)d_out;

    // plain: 2 stages x (18432 + 9216) = 55296 B ; Cs = 128*65*4 = 33280 B
    // split: 1 stage x 2 x (18432 + 9216) = 55296 B -> 3 CTAs/SM
    const int SMB_P = 55296;
    const int SMB_S = 55296;

    cudaFuncSetAttribute(gemm_mma<0,0,0,0,0,64,3>, cudaFuncAttributeMaxDynamicSharedMemorySize, SMB_P);
    cudaFuncSetAttribute(gemm_mma<0,1,0,0,0,64,3>, cudaFuncAttributeMaxDynamicSharedMemorySize, SMB_P);
    cudaFuncSetAttribute(gemm_mma<0,1,0,1,0,64,3>, cudaFuncAttributeMaxDynamicSharedMemorySize, SMB_P);
    cudaFuncSetAttribute(gemm_mma<1,3,0,0,0,64,3>, cudaFuncAttributeMaxDynamicSharedMemorySize, SMB_S);
    cudaFuncSetAttribute(gemm_mma<0,6,1,1,1,64,3>, cudaFuncAttributeMaxDynamicSharedMemorySize, SMB_P);

    prep_flags<<<1, 64>>>(rs, ini, sel);
    build_S<<<dim3(DP / 8, NAG), 256>>>(cov);
    fill_X<<<dim3(144, NAG), 256>>>();

    dim3 g12(12, 1, NAG);
    // buffers: 0=S, 1=XA, 2=XB, 3=Y/D
    // plain Newton iter 1
    gemm_mma<0,0,0,0,0,64,3><<<g12, 256, SMB_P>>>(0, 1, 0, 3, nullptr);  // Y  = S*XA        (hi)
    gemm_mma<0,1,0,0,0,64,3><<<g12, 256, SMB_P>>>(1, 3, 1, 2, nullptr);  // XB = 2XA - XA*Y  (hi)
    // plain Newton iter 2
    gemm_mma<0,0,0,0,0,64,3><<<g12, 256, SMB_P>>>(0, 2, 0, 3, nullptr);  // Y  = S*XB        (hi)
    gemm_mma<0,1,0,1,0,64,3><<<g12, 256, SMB_P>>>(2, 3, 2, 1, nullptr);  // XA = 2XB - XB*Y  (hi+lo)
    // quadratic finish: Xf = XA - XA*D, D = S*XA - I (split)
    gemm_mma<1,3,0,0,0,64,3><<<g12, 256, SMB_S>>>(0, 1, 0, 3, nullptr);  // D  = S*XA - I    (split, hi)
    gemm_mma<0,6,1,1,1,64,3><<<g12, 256, SMB_P>>>(1, 3, 1, 2, out + OUT_COV); // Xf = XA - XA*D -> XB (+cov)

    finalize_cov_rest<<<dim3((DD / 4 + 255) / 256, NAG), 256>>>(cov, out);
    finalize_mean<<<NAG, 256>>>(mean, obs, out, 2);
}

// round 15
// speedup vs baseline: 1.0195x; 1.0195x over previous
#include <cuda_runtime.h>
#include <cuda_bf16.h>
#include <cstdint>
#include <cstddef>

// ---------------- problem constants ----------------
#define NAG 64           // B*A
#define DIN 360          // logical dim
#define DD  (DIN*DIN)
#define MODE_LEN 60
#define DP  384          // padded dim (3 x 128)
#define DP2 (DP*DP)

// ---------------- scratch: bf16 hi/lo pairs ----------------
__device__ __align__(128) __nv_bfloat16 g_Sh [(size_t)NAG*DP2];
__device__ __align__(128) __nv_bfloat16 g_Sl [(size_t)NAG*DP2];
__device__ __align__(128) __nv_bfloat16 g_XAh[(size_t)NAG*DP2];
__device__ __align__(128) __nv_bfloat16 g_XAl[(size_t)NAG*DP2];
__device__ __align__(128) __nv_bfloat16 g_XBh[(size_t)NAG*DP2];
__device__ __align__(128) __nv_bfloat16 g_XBl[(size_t)NAG*DP2];
__device__ __align__(128) __nv_bfloat16 g_Yh [(size_t)NAG*DP2];
__device__ __align__(128) __nv_bfloat16 g_Yl [(size_t)NAG*DP2];
__device__ float g_rowsum[NAG * DIN];
__device__ float g_r[NAG];
__device__ int   g_upd[NAG];
__device__ int   g_initnew[NAG];
__device__ int   g_initout[NAG];

__device__ __forceinline__ __nv_bfloat16* selH(int s) {
    switch (s) {
        case 0:  return g_Sh;
        case 1:  return g_XAh;
        case 2:  return g_XBh;
        default: return g_Yh;
    }
}
__device__ __forceinline__ __nv_bfloat16* selL(int s) {
    switch (s) {
        case 0:  return g_Sl;
        case 1:  return g_XAl;
        case 2:  return g_XBl;
        default: return g_Yl;
    }
}

__device__ __forceinline__ int srcIdx(int g) {
    int l = g % MODE_LEN;
    return (l < MODE_LEN - 2) ? (g + 2) : g;
}

// ---------------- small helpers ----------------
__device__ __forceinline__ uint32_t smem_u32(const void* p) {
    uint32_t a;
    asm("{ .reg .u64 t; cvta.to.shared.u64 t, %1; cvt.u32.u64 %0, t; }"
        : "=r"(a) : "l"(p));
    return a;
}
__device__ __forceinline__ uint32_t pack_bf2(float x, float y) {
    __nv_bfloat162 t = __floats2bfloat162_rn(x, y);
    return *reinterpret_cast<uint32_t*>(&t);
}
__device__ __forceinline__ float2 bf2f(uint32_t u) {
    __nv_bfloat162 t = *reinterpret_cast<__nv_bfloat162*>(&u);
    return make_float2(__bfloat162float(t.x), __bfloat162float(t.y));
}
__device__ __forceinline__ void split2(float a, float b, uint32_t& h, uint32_t& l) {
    __nv_bfloat16 ah = __float2bfloat16_rn(a), bh = __float2bfloat16_rn(b);
    float ar = a - __bfloat162float(ah), br = b - __bfloat162float(bh);
    __nv_bfloat162 t; t.x = ah; t.y = bh;
    h = *reinterpret_cast<uint32_t*>(&t);
    l = pack_bf2(ar, br);
}

// ---------------- flag dtype sniffing (validated round 2) ----------------
__device__ int detect_mode(const unsigned char* p) {
    int n_off = 0, n_3f = 0;
    for (int t = 0; t < 64; t++) {
        unsigned char b = p[t];
        if ((t & 3) && b) n_off++;
        if (((t & 3) == 3) && b == 0x3F) n_3f++;
    }
    if (n_off == 0) return 1;
    if (n_3f > 0)  return 2;
    return 0;
}
__device__ __forceinline__ bool read_flag(const void* p, int t, int mode) {
    if (mode == 1) return ((const int*)p)[t] != 0;
    if (mode == 2) return ((const float*)p)[t] != 0.0f;
    return ((const unsigned char*)p)[t] != 0;
}

__global__ void prep_flags(const float* __restrict__ rs,
                           const void* __restrict__ ini,
                           const void* __restrict__ sel) {
    __shared__ int mode_i, mode_s;
    if (threadIdx.x == 0) {
        mode_i = detect_mode((const unsigned char*)ini);
        mode_s = detect_mode((const unsigned char*)sel);
    }
    __syncthreads();
    int t = threadIdx.x;
    if (t >= NAG) return;
    float r = rs[t] + 1.0f;
    bool i8 = read_flag(ini, t, mode_i);
    bool s8 = read_flag(sel, t, mode_s);
    g_r[t] = r;
    g_upd[t] = (s8 && i8);
    g_initnew[t] = (s8 && !i8);
    g_initout[t] = (s8 || i8);
}

// ---------------- S = A P A^T + (1+r)I -> split bf16 + fused Gershgorin ---
__global__ void build_S(const float* __restrict__ cov) {
    int a = blockIdx.y;
    if (!g_upd[a]) return;
    int warp = threadIdx.x >> 5, lane = threadIdx.x & 31;
    int i = blockIdx.x * 8 + warp;
    float r = g_r[a];
    size_t off = (size_t)a * DP2 + (size_t)i * DP + lane * 12;
    if (i < DIN) {
        const float* row = cov + (size_t)a * DD + (size_t)srcIdx(i) * DIN;
        float asum = 0.0f;
        #pragma unroll
        for (int g = 0; g < 3; g++) {
            float v[4];
            #pragma unroll
            for (int q = 0; q < 4; q++) {
                int j = lane * 12 + g * 4 + q;
                float x = 0.0f;
                if (j < DIN) {
                    x = row[srcIdx(j)];
                    if (j == i) x += 1.0f + r;
                }
                v[q] = x;
                asum += fabsf(x);
            }
            uint32_t h0, l0, h1, l1;
            split2(v[0], v[1], h0, l0);
            split2(v[2], v[3], h1, l1);
            *(uint2*)(g_Sh + off + g * 4) = make_uint2(h0, h1);
            *(uint2*)(g_Sl + off + g * 4) = make_uint2(l0, l1);
        }
        #pragma unroll
        for (int o = 16; o; o >>= 1) asum += __shfl_xor_sync(0xffffffffu, asum, o);
        if (lane == 0) g_rowsum[a * DIN + i] = asum;
    } else {
        #pragma unroll
        for (int g = 0; g < 3; g++) {
            float v[4];
            #pragma unroll
            for (int q = 0; q < 4; q++)
                v[q] = (lane * 12 + g * 4 + q == i) ? 1.0f : 0.0f;
            uint32_t h0, l0, h1, l1;
            split2(v[0], v[1], h0, l0);
            split2(v[2], v[3], h1, l1);
            *(uint2*)(g_Sh + off + g * 4) = make_uint2(h0, h1);
            *(uint2*)(g_Sl + off + g * 4) = make_uint2(l0, l1);
        }
    }
}

// X0 = 2c I - c^2 S -> split bf16 into XA. Gershgorin max fused per block.
__global__ void fill_X(void) {
    int a = blockIdx.y;
    if (!g_upd[a]) return;
    int tid = threadIdx.x;
    __shared__ float wm8[8];
    __shared__ float sc;
    float m = 0.0f;
    for (int i = tid; i < DIN; i += 256) m = fmaxf(m, g_rowsum[a * DIN + i]);
    #pragma unroll
    for (int o = 16; o; o >>= 1) m = fmaxf(m, __shfl_xor_sync(0xffffffffu, m, o));
    if ((tid & 31) == 0) wm8[tid >> 5] = m;
    __syncthreads();
    if (tid == 0) {
        float G = 0.0f;
        #pragma unroll
        for (int w = 0; w < 8; w++) G = fmaxf(G, wm8[w]);
        sc = 2.0f / (1.0f + g_r[a] + G * 1.0002f);
    }
    __syncthreads();
    float c = sc;

    int e4 = blockIdx.x * 256 + tid;   // < DP2/4 = 36864
    int i = e4 / 96;
    int jj = (e4 - i * 96) * 4;
    size_t off = (size_t)a * DP2 + (size_t)i * DP + jj;
    uint2 sh = *(const uint2*)(g_Sh + off);
    uint2 sl = *(const uint2*)(g_Sl + off);
    float2 h0 = bf2f(sh.x), h1 = bf2f(sh.y);
    float2 l0 = bf2f(sl.x), l1 = bf2f(sl.y);
    float s0 = h0.x + l0.x, s1 = h0.y + l0.y, s2 = h1.x + l1.x, s3 = h1.y + l1.y;
    float c2 = c * c;
    float v0 = ((i == jj)     ? 2.0f * c : 0.0f) - c2 * s0;
    float v1 = ((i == jj + 1) ? 2.0f * c : 0.0f) - c2 * s1;
    float v2 = ((i == jj + 2) ? 2.0f * c : 0.0f) - c2 * s2;
    float v3 = ((i == jj + 3) ? 2.0f * c : 0.0f) - c2 * s3;
    uint32_t a0, b0, a1, b1;
    split2(v0, v1, a0, b0);
    split2(v2, v3, a1, b1);
    *(uint2*)(g_XAh + off) = make_uint2(a0, a1);
    *(uint2*)(g_XAl + off) = make_uint2(b0, b1);
}

// ================= pipelined mma.sync bf16 GEMM (symmetric tiles) =====
// KC = k-chunk (64 plain / 32 split), LDT = KC + 8 (conflict-free ldmatrix).

__device__ __forceinline__ void ldm_x4(uint32_t* r, uint32_t addr) {
    asm volatile("ldmatrix.sync.aligned.m8n8.x4.shared.b16 {%0,%1,%2,%3}, [%4];"
                 : "=r"(r[0]), "=r"(r[1]), "=r"(r[2]), "=r"(r[3]) : "r"(addr));
}
__device__ __forceinline__ void mma_bf16(float* d, const uint32_t* a, const uint32_t* b) {
    asm volatile(
        "mma.sync.aligned.m16n8k16.row.col.f32.bf16.bf16.f32 "
        "{%0,%1,%2,%3}, {%4,%5,%6,%7}, {%8,%9}, {%0,%1,%2,%3};"
        : "+f"(d[0]), "+f"(d[1]), "+f"(d[2]), "+f"(d[3])
        : "r"(a[0]), "r"(a[1]), "r"(a[2]), "r"(a[3]), "r"(b[0]), "r"(b[1]));
}

// stage one ROWSxKC bf16 panel global -> SMEM (row stride LDT halves)
template<int ROWS, int KC>
__device__ __forceinline__ void stageP(const __nv_bfloat16* __restrict__ g,
                                       int row0, int k0, uint32_t dst, int tid) {
    constexpr int LDTc = KC + 8;
    constexpr int PPR = KC / 8;       // 16B parts per row
    const __nv_bfloat16* src0 = g + (size_t)row0 * DP + k0;
    #pragma unroll
    for (int i = 0; i < ROWS * PPR / 256; i++) {
        int id = i * 256 + tid;
        int row = id / PPR, part = id % PPR;
        uint32_t d = dst + (uint32_t)(row * LDTc + part * 8) * 2;
        const void* s = src0 + (size_t)row * DP + part * 8;
        asm volatile("cp.async.cg.shared.global [%0], [%1], 16;"
                     :: "r"(d), "l"(s));
    }
}

// SPLIT=0: hi*hi. SPLIT=1: 4 panels per stage, 3 passes. Always double-buffered.
// MODE 0: C = A*B ; MODE 1: C = 2X - A*B ; MODE 3: C = A*B - I ;
// MODE 6: C = X - A*B (quadratic finish).
// XLO: read X lo plane. WRITELO: write C lo plane.
// FINAL: also write r*I - r^2*C to outp (fp32). MINC: min CTAs/SM. KC: k-chunk.
template<int SPLIT, int MODE, int XLO, int WRITELO, int FINAL, int NT, int MINC, int KC>
__global__ __launch_bounds__(256, MINC)
void gemm_mma(int sA, int sB, int sX, int sC, float* outp) {
    int z = blockIdx.z;
    if (!g_upd[z]) return;

    const int bim[12] = {0, 0, 0, 0, 0, 0, 1, 1, 1, 1, 2, 2};
    const int bjm[12] = {0, 1, 2, 3, 4, 5, 2, 3, 4, 5, 4, 5};
    int bi = bim[blockIdx.x], bj = bjm[blockIdx.x];
    int m0 = bi * 128, n0 = bj * NT;
    bool offd = ((bj >> 1) != bi);

    constexpr int LDTc = KC + 8;
    constexpr int PA_Ec = 128 * LDTc;
    constexpr int PA_Bc = PA_Ec * 2;
    constexpr int PB_Ec = NT * LDTc;
    constexpr int PB_Bc = PB_Ec * 2;
    constexpr int MT = 2;              // NT = 64
    constexpr int LDCn = 65;
    constexpr int STAGE_E = (SPLIT ? 2 : 1) * (PA_Ec + PB_Ec);
    constexpr uint32_t STAGE_B = STAGE_E * 2;
    constexpr int NCH = 384 / KC;

    size_t zo = (size_t)z * DP2;
    const __nv_bfloat16* AH = selH(sA) + zo;
    const __nv_bfloat16* AL = selL(sA) + zo;
    const __nv_bfloat16* BH = selH(sB) + zo;
    const __nv_bfloat16* BL = selL(sB) + zo;
    const __nv_bfloat16* XH = selH(sX) + zo;
    const __nv_bfloat16* XL = selL(sX) + zo;
    __nv_bfloat16* CH = selH(sC) + zo;
    __nv_bfloat16* CL = selL(sC) + zo;

    extern __shared__ __align__(16) __nv_bfloat16 sm[];
    float* Cs = reinterpret_cast<float*>(sm);
    uint32_t sbase = smem_u32(sm);

    int tid = threadIdx.x, wid = tid >> 5, lane = tid & 31;
    int wm = (wid & 3) * 32;
    int wn = (wid >> 2) * 32;

    float acc[MT][4][4];
    #pragma unroll
    for (int i = 0; i < MT; i++)
        #pragma unroll
        for (int j = 0; j < 4; j++)
            #pragma unroll
            for (int q = 0; q < 4; q++) acc[i][j][q] = 0.0f;

    int lt = lane >> 3, lr = lane & 7;
    int a_row = (lt & 1) * 8 + lr;
    int a_col = (lt >> 1) * 8;
    int b_row = (lt >> 1) * 8 + lr;
    int b_col = (lt & 1) * 8;

    auto do_stage = [&](int kc, int b) {
        uint32_t base = sbase + (uint32_t)b * STAGE_B;
        int k0 = kc * KC;
        stageP<128, KC>(AH, m0, k0, base, tid);
        stageP<NT, KC>(BH, n0, k0, base + PA_Bc, tid);
        if (SPLIT) {
            stageP<128, KC>(AL, m0, k0, base + PA_Bc + PB_Bc, tid);
            stageP<NT, KC>(BL, n0, k0, base + 2 * PA_Bc + PB_Bc, tid);
        }
        asm volatile("cp.async.commit_group;");
    };

    auto do_compute = [&](int cur) {
        const __nv_bfloat16* At  = sm + (size_t)cur * STAGE_E;
        const __nv_bfloat16* Bt  = At + PA_Ec;
        const __nv_bfloat16* Alt = Bt + PB_Ec;
        const __nv_bfloat16* Blt = Alt + PA_Ec;

        #pragma unroll
        for (int ks = 0; ks < KC / 16; ks++) {
            int kk = ks * 16;
            uint32_t ah[MT][4], bh[4][2];
            #pragma unroll
            for (int mt = 0; mt < MT; mt++)
                ldm_x4(ah[mt], smem_u32(&At[(wm + mt * 16 + a_row) * LDTc + kk + a_col]));
            #pragma unroll
            for (int np = 0; np < 2; np++) {
                uint32_t r[4];
                ldm_x4(r, smem_u32(&Bt[(wn + np * 16 + b_row) * LDTc + kk + b_col]));
                bh[np * 2][0] = r[0]; bh[np * 2][1] = r[1];
                bh[np * 2 + 1][0] = r[2]; bh[np * 2 + 1][1] = r[3];
            }
            #pragma unroll
            for (int mt = 0; mt < MT; mt++)
                #pragma unroll
                for (int nt = 0; nt < 4; nt++)
                    mma_bf16(acc[mt][nt], ah[mt], bh[nt]);

            if (SPLIT) {
                uint32_t bl[4][2];
                #pragma unroll
                for (int np = 0; np < 2; np++) {
                    uint32_t r[4];
                    ldm_x4(r, smem_u32(&Blt[(wn + np * 16 + b_row) * LDTc + kk + b_col]));
                    bl[np * 2][0] = r[0]; bl[np * 2][1] = r[1];
                    bl[np * 2 + 1][0] = r[2]; bl[np * 2 + 1][1] = r[3];
                }
                #pragma unroll
                for (int mt = 0; mt < MT; mt++)
                    #pragma unroll
                    for (int nt = 0; nt < 4; nt++)
                        mma_bf16(acc[mt][nt], ah[mt], bl[nt]);
                uint32_t al[MT][4];
                #pragma unroll
                for (int mt = 0; mt < MT; mt++)
                    ldm_x4(al[mt], smem_u32(&Alt[(wm + mt * 16 + a_row) * LDTc + kk + a_col]));
                #pragma unroll
                for (int mt = 0; mt < MT; mt++)
                    #pragma unroll
                    for (int nt = 0; nt < 4; nt++)
                        mma_bf16(acc[mt][nt], al[mt], bh[nt]);
            }
        }
    };

    do_stage(0, 0);
    for (int kc = 0; kc < NCH; kc++) {
        asm volatile("cp.async.wait_group 0;");
        __syncthreads();   // certifies compute(kc-1) done; buffer kc+1 free
        if (kc + 1 < NCH) do_stage(kc + 1, (kc + 1) & 1);
        do_compute(kc & 1);
    }
    __syncthreads();   // protect Cs reuse of staging smem

    // ---- epilogue ----
    float r = g_r[z];
    float rr = -r * r;
    #pragma unroll
    for (int mt = 0; mt < MT; mt++) {
        int rl0 = wm + mt * 16 + (lane >> 2);
        #pragma unroll
        for (int nt = 0; nt < 4; nt++) {
            int cl0 = wn + nt * 8 + 2 * (lane & 3);
            float v00 = acc[mt][nt][0], v01 = acc[mt][nt][1];
            float v10 = acc[mt][nt][2], v11 = acc[mt][nt][3];
            size_t g0 = (size_t)(m0 + rl0) * DP + n0 + cl0;
            size_t g1 = g0 + 8 * DP;
            int gi0 = m0 + rl0, gj = n0 + cl0;
            if (MODE == 1 || MODE == 6) {
                float2 xh0 = bf2f(*(const uint32_t*)(XH + g0));
                float2 xh1 = bf2f(*(const uint32_t*)(XH + g1));
                float x00 = xh0.x, x01 = xh0.y, x10 = xh1.x, x11 = xh1.y;
                if (XLO) {
                    float2 xl0 = bf2f(*(const uint32_t*)(XL + g0));
                    float2 xl1 = bf2f(*(const uint32_t*)(XL + g1));
                    x00 += xl0.x; x01 += xl0.y; x10 += xl1.x; x11 += xl1.y;
                }
                if (MODE == 1) {
                    v00 = 2.0f * x00 - v00; v01 = 2.0f * x01 - v01;
                    v10 = 2.0f * x10 - v10; v11 = 2.0f * x11 - v11;
                } else {                 // MODE 6: C = X - A*B
                    v00 = x00 - v00; v01 = x01 - v01;
                    v10 = x10 - v10; v11 = x11 - v11;
                }
            }
            if (MODE == 3) {   // C = A*B - I
                if (gi0 == gj)     v00 -= 1.0f;
                if (gi0 == gj + 1) v01 -= 1.0f;
                if (gi0 + 8 == gj)     v10 -= 1.0f;
                if (gi0 + 8 == gj + 1) v11 -= 1.0f;
            }
            uint32_t h, l;
            split2(v00, v01, h, l);
            *(uint32_t*)(CH + g0) = h;
            if (WRITELO) *(uint32_t*)(CL + g0) = l;
            split2(v10, v11, h, l);
            *(uint32_t*)(CH + g1) = h;
            if (WRITELO) *(uint32_t*)(CL + g1) = l;
            if (FINAL) {
                if (gj < DIN) {
                    if (gi0 < DIN) {
                        float2 o;
                        o.x = rr * v00 + ((gi0 == gj) ? r : 0.0f);
                        o.y = rr * v01 + ((gi0 == gj + 1) ? r : 0.0f);
                        *(float2*)(outp + (size_t)z * DD + (size_t)gi0 * DIN + gj) = o;
                    }
                    int gi1 = gi0 + 8;
                    if (gi1 < DIN) {
                        float2 o;
                        o.x = rr * v10 + ((gi1 == gj) ? r : 0.0f);
                        o.y = rr * v11 + ((gi1 == gj + 1) ? r : 0.0f);
                        *(float2*)(outp + (size_t)z * DD + (size_t)gi1 * DIN + gj) = o;
                    }
                }
            }
            if (offd) {
                Cs[rl0 * LDCn + cl0] = v00;
                Cs[rl0 * LDCn + cl0 + 1] = v01;
                Cs[(rl0 + 8) * LDCn + cl0] = v10;
                Cs[(rl0 + 8) * LDCn + cl0 + 1] = v11;
            }
        }
    }

    if (offd) {
        __syncthreads();
        #pragma unroll
        for (int it = 0; it < NT / 4; it++) {
            int p = it * 256 + tid;
            int cc = p >> 6, mp = (p & 63) * 2;
            float v0 = Cs[mp * LDCn + cc];
            float v1 = Cs[(mp + 1) * LDCn + cc];
            int gi = n0 + cc, gj = m0 + mp;
            size_t g = (size_t)gi * DP + gj;
            uint32_t h, l;
            split2(v0, v1, h, l);
            *(uint32_t*)(CH + g) = h;
            if (WRITELO) *(uint32_t*)(CL + g) = l;
            if (FINAL) {
                if (gi < DIN && gj < DIN) {
                    float2 o;
                    o.x = rr * v0;
                    o.y = rr * v1;
                    *(float2*)(outp + (size_t)z * DD + (size_t)gi * DIN + gj) = o;
                }
            }
        }
    }
}

// ---------------- outputs ----------------
#define OUT_MEAN 0
#define OUT_COV  (NAG * DIN)
#define OUT_INIT (NAG * DIN + NAG * DD)

__global__ void finalize_cov_rest(const float* __restrict__ cov,
                                  float* __restrict__ out) {
    int a = blockIdx.y;
    if (g_upd[a]) return;
    int e4 = blockIdx.x * blockDim.x + threadIdx.x;
    if (e4 >= DD / 4) return;
    int i = e4 / 90;
    int jj = (e4 - i * 90) * 4;
    float4 o = *(const float4*)(cov + (size_t)a * DD + (size_t)i * DIN + jj);
    if (g_initnew[a]) {
        if (i >= jj && i < jj + 4) (&o.x)[i - jj] += g_r[a];
    }
    *(float4*)(out + OUT_COV + (size_t)a * DD + (size_t)i * DIN + jj) = o;
}

__global__ void finalize_mean(const float* __restrict__ mean_in,
                              const float* __restrict__ obs,
                              float* __restrict__ out, int sinv) {
    int a = blockIdx.x;
    int tid = threadIdx.x;
    __shared__ float v[DIN];

    if (tid == 0) out[OUT_INIT + a] = g_initout[a] ? 1.0f : 0.0f;

    const float* m = mean_in + (size_t)a * DIN;
    const float* o = obs + (size_t)a * DIN;
    float* om = out + OUT_MEAN + (size_t)a * DIN;

    if (g_initnew[a]) {
        for (int i = tid; i < DIN; i += blockDim.x) om[i] = o[i];
    } else if (g_upd[a]) {
        float r = g_r[a];
        const __nv_bfloat16* Xh = selH(sinv) + (size_t)a * DP2;
        const __nv_bfloat16* Xl = selL(sinv) + (size_t)a * DP2;
        for (int j = tid; j < DIN; j += blockDim.x) v[j] = o[j] - m[srcIdx(j)];
        __syncthreads();
        int warp = tid >> 5, lane = tid & 31;
        for (int i = warp; i < DIN; i += 8) {
            float s = 0.0f;
            size_t row = (size_t)i * DP;
            for (int j = lane; j < DIN; j += 32)
                s += (__bfloat162float(Xh[row + j]) + __bfloat162float(Xl[row + j])) * v[j];
            #pragma unroll
            for (int off = 16; off; off >>= 1) s += __shfl_xor_sync(0xffffffffu, s, off);
            if (lane == 0) om[i] = o[i] - r * s;
        }
    } else {
        for (int i = tid; i < DIN; i += blockDim.x) om[i] = m[i];
    }
}

// ---------------- launch ----------------
extern "C" void kernel_launch(void* const* d_in, const int* in_sizes, int n_in,
                              void* d_out, int out_size) {
    const float* mean = (const float*)d_in[0];
    const float* cov  = (const float*)d_in[1];
    const float* obs  = (const float*)d_in[2];
    const float* rs   = (const float*)d_in[3];
    const void*  ini  = d_in[4];
    const void*  sel  = d_in[5];
    float* out = (float*)d_out;

    // plain KC=64: 2 stages x (128+64)*72*2 = 55296 B -> 3 CTAs/SM
    // split KC=32: 2 stages x 2 x (128+64)*40*2 = 61440 B -> 3 CTAs/SM
    const int SMB_P = 55296;
    const int SMB_S = 61440;

    cudaFuncSetAttribute(gemm_mma<0,0,0,0,0,64,3,64>, cudaFuncAttributeMaxDynamicSharedMemorySize, SMB_P);
    cudaFuncSetAttribute(gemm_mma<0,1,0,0,0,64,3,64>, cudaFuncAttributeMaxDynamicSharedMemorySize, SMB_P);
    cudaFuncSetAttribute(gemm_mma<0,1,0,1,0,64,3,64>, cudaFuncAttributeMaxDynamicSharedMemorySize, SMB_P);
    cudaFuncSetAttribute(gemm_mma<1,3,0,0,0,64,3,32>, cudaFuncAttributeMaxDynamicSharedMemorySize, SMB_S);
    cudaFuncSetAttribute(gemm_mma<0,6,1,1,1,64,3,64>, cudaFuncAttributeMaxDynamicSharedMemorySize, SMB_P);

    prep_flags<<<1, 64>>>(rs, ini, sel);
    build_S<<<dim3(DP / 8, NAG), 256>>>(cov);
    fill_X<<<dim3(144, NAG), 256>>>();

    dim3 g12(12, 1, NAG);
    // buffers: 0=S, 1=XA, 2=XB, 3=Y/D
    // plain Newton iter 1
    gemm_mma<0,0,0,0,0,64,3,64><<<g12, 256, SMB_P>>>(0, 1, 0, 3, nullptr);  // Y  = S*XA       (hi)
    gemm_mma<0,1,0,0,0,64,3,64><<<g12, 256, SMB_P>>>(1, 3, 1, 2, nullptr);  // XB = 2XA - XA*Y (hi)
    // plain Newton iter 2
    gemm_mma<0,0,0,0,0,64,3,64><<<g12, 256, SMB_P>>>(0, 2, 0, 3, nullptr);  // Y  = S*XB       (hi)
    gemm_mma<0,1,0,1,0,64,3,64><<<g12, 256, SMB_P>>>(2, 3, 2, 1, nullptr);  // XA = 2XB - XB*Y (hi+lo)
    // quadratic finish: Xf = XA - XA*D, D = S*XA - I (split, k32 double-buffered)
    gemm_mma<1,3,0,0,0,64,3,32><<<g12, 256, SMB_S>>>(0, 1, 0, 3, nullptr);  // D  = S*XA - I   (split, hi)
    gemm_mma<0,6,1,1,1,64,3,64><<<g12, 256, SMB_P>>>(1, 3, 1, 2, out + OUT_COV); // Xf = XA - XA*D (+cov)

    finalize_cov_rest<<<dim3((DD / 4 + 255) / 256, NAG), 256>>>(cov, out);
    finalize_mean<<<NAG, 256>>>(mean, obs, out, 2);
}

// round 16
// speedup vs baseline: 1.0467x; 1.0267x over previous
#include <cuda_runtime.h>
#include <cuda_bf16.h>
#include <cstdint>
#include <cstddef>

// ---------------- problem constants ----------------
#define NAG 64           // B*A
#define DIN 360          // logical dim
#define DD  (DIN*DIN)
#define MODE_LEN 60
#define DP  384          // padded dim (3 x 128)
#define DP2 (DP*DP)

// out layout (f32): [mean 64*360][cov 64*360*360][initialized 64]
#define OUT_MEAN 0
#define OUT_COV  (NAG * DIN)
#define OUT_INIT (NAG * DIN + NAG * DD)

// ---------------- scratch: bf16 hi/lo pairs ----------------
__device__ __align__(128) __nv_bfloat16 g_Sh [(size_t)NAG*DP2];
__device__ __align__(128) __nv_bfloat16 g_Sl [(size_t)NAG*DP2];
__device__ __align__(128) __nv_bfloat16 g_XAh[(size_t)NAG*DP2];
__device__ __align__(128) __nv_bfloat16 g_XAl[(size_t)NAG*DP2];
__device__ __align__(128) __nv_bfloat16 g_XBh[(size_t)NAG*DP2];
__device__ __align__(128) __nv_bfloat16 g_XBl[(size_t)NAG*DP2];
__device__ __align__(128) __nv_bfloat16 g_Yh [(size_t)NAG*DP2];
__device__ __align__(128) __nv_bfloat16 g_Yl [(size_t)NAG*DP2];
__device__ float g_rowsum[NAG * DIN];
__device__ float g_r[NAG];
__device__ int   g_upd[NAG];
__device__ int   g_initnew[NAG];
__device__ int   g_initout[NAG];

__device__ __forceinline__ __nv_bfloat16* selH(int s) {
    switch (s) {
        case 0:  return g_Sh;
        case 1:  return g_XAh;
        case 2:  return g_XBh;
        default: return g_Yh;
    }
}
__device__ __forceinline__ __nv_bfloat16* selL(int s) {
    switch (s) {
        case 0:  return g_Sl;
        case 1:  return g_XAl;
        case 2:  return g_XBl;
        default: return g_Yl;
    }
}

__device__ __forceinline__ int srcIdx(int g) {
    int l = g % MODE_LEN;
    return (l < MODE_LEN - 2) ? (g + 2) : g;
}

// ---------------- small helpers ----------------
__device__ __forceinline__ uint32_t smem_u32(const void* p) {
    uint32_t a;
    asm("{ .reg .u64 t; cvta.to.shared.u64 t, %1; cvt.u32.u64 %0, t; }"
        : "=r"(a) : "l"(p));
    return a;
}
__device__ __forceinline__ uint32_t pack_bf2(float x, float y) {
    __nv_bfloat162 t = __floats2bfloat162_rn(x, y);
    return *reinterpret_cast<uint32_t*>(&t);
}
__device__ __forceinline__ float2 bf2f(uint32_t u) {
    __nv_bfloat162 t = *reinterpret_cast<__nv_bfloat162*>(&u);
    return make_float2(__bfloat162float(t.x), __bfloat162float(t.y));
}
__device__ __forceinline__ void split2(float a, float b, uint32_t& h, uint32_t& l) {
    __nv_bfloat16 ah = __float2bfloat16_rn(a), bh = __float2bfloat16_rn(b);
    float ar = a - __bfloat162float(ah), br = b - __bfloat162float(bh);
    __nv_bfloat162 t; t.x = ah; t.y = bh;
    h = *reinterpret_cast<uint32_t*>(&t);
    l = pack_bf2(ar, br);
}

// ---------------- flag dtype sniffing (validated round 2) ----------------
__device__ int detect_mode(const unsigned char* p) {
    int n_off = 0, n_3f = 0;
    for (int t = 0; t < 64; t++) {
        unsigned char b = p[t];
        if ((t & 3) && b) n_off++;
        if (((t & 3) == 3) && b == 0x3F) n_3f++;
    }
    if (n_off == 0) return 1;
    if (n_3f > 0)  return 2;
    return 0;
}
__device__ __forceinline__ bool read_flag(const void* p, int t, int mode) {
    if (mode == 1) return ((const int*)p)[t] != 0;
    if (mode == 2) return ((const float*)p)[t] != 0.0f;
    return ((const unsigned char*)p)[t] != 0;
}

__global__ void prep_flags(const float* __restrict__ rs,
                           const void* __restrict__ ini,
                           const void* __restrict__ sel) {
    __shared__ int mode_i, mode_s;
    if (threadIdx.x == 0) {
        mode_i = detect_mode((const unsigned char*)ini);
        mode_s = detect_mode((const unsigned char*)sel);
    }
    __syncthreads();
    int t = threadIdx.x;
    if (t >= NAG) return;
    float r = rs[t] + 1.0f;
    bool i8 = read_flag(ini, t, mode_i);
    bool s8 = read_flag(sel, t, mode_s);
    g_r[t] = r;
    g_upd[t] = (s8 && i8);
    g_initnew[t] = (s8 && !i8);
    g_initout[t] = (s8 || i8);
}

// ---------------- build_S: all agents ----------------
// upd agents:    S = A P A^T + (1+r)I -> split bf16 + fused Gershgorin rowsum
// non-upd:       write cov output directly (cov + rI for init-new, else cov)
// 256 threads = 8 warps; warp owns one row; lane covers j = g*128 + lane*4.
__global__ void build_S(const float* __restrict__ cov, float* __restrict__ out) {
    int a = blockIdx.y;
    int warp = threadIdx.x >> 5, lane = threadIdx.x & 31;
    int i = blockIdx.x * 8 + warp;
    float r = g_r[a];

    if (g_upd[a]) {
        size_t off = (size_t)a * DP2 + (size_t)i * DP;
        if (i < DIN) {
            const float* row = cov + (size_t)a * DD + (size_t)srcIdx(i) * DIN;
            float asum = 0.0f;
            #pragma unroll
            for (int g = 0; g < 3; g++) {
                int j0 = g * 128 + lane * 4;
                float v[4];
                if (j0 + 3 < DIN && (j0 % MODE_LEN) <= MODE_LEN - 6) {
                    // srcIdx(j) = j+2 for all four -> two float2 loads
                    float2 p0 = *(const float2*)(row + j0 + 2);
                    float2 p1 = *(const float2*)(row + j0 + 4);
                    v[0] = p0.x; v[1] = p0.y; v[2] = p1.x; v[3] = p1.y;
                } else {
                    #pragma unroll
                    for (int q = 0; q < 4; q++) {
                        int j = j0 + q;
                        v[q] = (j < DIN) ? row[srcIdx(j)] : 0.0f;
                    }
                }
                if (i >= j0 && i < j0 + 4) v[i - j0] += 1.0f + r;
                asum += fabsf(v[0]) + fabsf(v[1]) + fabsf(v[2]) + fabsf(v[3]);
                uint32_t h0, l0, h1, l1;
                split2(v[0], v[1], h0, l0);
                split2(v[2], v[3], h1, l1);
                *(uint2*)(g_Sh + off + j0) = make_uint2(h0, h1);
                *(uint2*)(g_Sl + off + j0) = make_uint2(l0, l1);
            }
            #pragma unroll
            for (int o = 16; o; o >>= 1) asum += __shfl_xor_sync(0xffffffffu, asum, o);
            if (lane == 0) g_rowsum[a * DIN + i] = asum;
        } else {
            // pad rows: identity
            #pragma unroll
            for (int g = 0; g < 3; g++) {
                int j0 = g * 128 + lane * 4;
                float v[4];
                #pragma unroll
                for (int q = 0; q < 4; q++) v[q] = (j0 + q == i) ? 1.0f : 0.0f;
                uint32_t h0, l0, h1, l1;
                split2(v[0], v[1], h0, l0);
                split2(v[2], v[3], h1, l1);
                *(uint2*)(g_Sh + off + j0) = make_uint2(h0, h1);
                *(uint2*)(g_Sl + off + j0) = make_uint2(l0, l1);
            }
        }
    } else {
        // non-update agent: emit cov output now (overlaps with pipeline front)
        if (i >= DIN) return;
        bool inew = g_initnew[a];
        const float* src = cov + (size_t)a * DD + (size_t)i * DIN;
        float* dst = out + OUT_COV + (size_t)a * DD + (size_t)i * DIN;
        #pragma unroll
        for (int g = 0; g < 3; g++) {
            int j0 = g * 128 + lane * 4;
            if (j0 < DIN) {
                float4 o = *(const float4*)(src + j0);
                if (inew && i >= j0 && i < j0 + 4) (&o.x)[i - j0] += r;
                *(float4*)(dst + j0) = o;
            }
        }
    }
}

// X0 = 2c I - c^2 S -> split bf16 into XA. Gershgorin max fused per block.
__global__ void fill_X(void) {
    int a = blockIdx.y;
    if (!g_upd[a]) return;
    int tid = threadIdx.x;
    __shared__ float wm8[8];
    __shared__ float sc;
    float m = 0.0f;
    for (int i = tid; i < DIN; i += 256) m = fmaxf(m, g_rowsum[a * DIN + i]);
    #pragma unroll
    for (int o = 16; o; o >>= 1) m = fmaxf(m, __shfl_xor_sync(0xffffffffu, m, o));
    if ((tid & 31) == 0) wm8[tid >> 5] = m;
    __syncthreads();
    if (tid == 0) {
        float G = 0.0f;
        #pragma unroll
        for (int w = 0; w < 8; w++) G = fmaxf(G, wm8[w]);
        sc = 2.0f / (1.0f + g_r[a] + G * 1.0002f);
    }
    __syncthreads();
    float c = sc;

    int e4 = blockIdx.x * 256 + tid;   // < DP2/4 = 36864
    int i = e4 / 96;
    int jj = (e4 - i * 96) * 4;
    size_t off = (size_t)a * DP2 + (size_t)i * DP + jj;
    uint2 sh = *(const uint2*)(g_Sh + off);
    uint2 sl = *(const uint2*)(g_Sl + off);
    float2 h0 = bf2f(sh.x), h1 = bf2f(sh.y);
    float2 l0 = bf2f(sl.x), l1 = bf2f(sl.y);
    float s0 = h0.x + l0.x, s1 = h0.y + l0.y, s2 = h1.x + l1.x, s3 = h1.y + l1.y;
    float c2 = c * c;
    float v0 = ((i == jj)     ? 2.0f * c : 0.0f) - c2 * s0;
    float v1 = ((i == jj + 1) ? 2.0f * c : 0.0f) - c2 * s1;
    float v2 = ((i == jj + 2) ? 2.0f * c : 0.0f) - c2 * s2;
    float v3 = ((i == jj + 3) ? 2.0f * c : 0.0f) - c2 * s3;
    uint32_t a0, b0, a1, b1;
    split2(v0, v1, a0, b0);
    split2(v2, v3, a1, b1);
    *(uint2*)(g_XAh + off) = make_uint2(a0, a1);
    *(uint2*)(g_XAl + off) = make_uint2(b0, b1);
}

// ================= pipelined mma.sync bf16 GEMM (symmetric tiles) =====
// KC = k-chunk (64 plain / 32 split), LDT = KC + 8 (conflict-free ldmatrix).

__device__ __forceinline__ void ldm_x4(uint32_t* r, uint32_t addr) {
    asm volatile("ldmatrix.sync.aligned.m8n8.x4.shared.b16 {%0,%1,%2,%3}, [%4];"
                 : "=r"(r[0]), "=r"(r[1]), "=r"(r[2]), "=r"(r[3]) : "r"(addr));
}
__device__ __forceinline__ void mma_bf16(float* d, const uint32_t* a, const uint32_t* b) {
    asm volatile(
        "mma.sync.aligned.m16n8k16.row.col.f32.bf16.bf16.f32 "
        "{%0,%1,%2,%3}, {%4,%5,%6,%7}, {%8,%9}, {%0,%1,%2,%3};"
        : "+f"(d[0]), "+f"(d[1]), "+f"(d[2]), "+f"(d[3])
        : "r"(a[0]), "r"(a[1]), "r"(a[2]), "r"(a[3]), "r"(b[0]), "r"(b[1]));
}

// stage one ROWSxKC bf16 panel global -> SMEM (row stride LDT halves)
template<int ROWS, int KC>
__device__ __forceinline__ void stageP(const __nv_bfloat16* __restrict__ g,
                                       int row0, int k0, uint32_t dst, int tid) {
    constexpr int LDTc = KC + 8;
    constexpr int PPR = KC / 8;       // 16B parts per row
    const __nv_bfloat16* src0 = g + (size_t)row0 * DP + k0;
    #pragma unroll
    for (int i = 0; i < ROWS * PPR / 256; i++) {
        int id = i * 256 + tid;
        int row = id / PPR, part = id % PPR;
        uint32_t d = dst + (uint32_t)(row * LDTc + part * 8) * 2;
        const void* s = src0 + (size_t)row * DP + part * 8;
        asm volatile("cp.async.cg.shared.global [%0], [%1], 16;"
                     :: "r"(d), "l"(s));
    }
}

// SPLIT=0: hi*hi. SPLIT=1: 4 panels per stage, 3 passes. Always double-buffered.
// MODE 0: C = A*B ; MODE 1: C = 2X - A*B ; MODE 3: C = A*B - I ;
// MODE 6: C = X - A*B (quadratic finish).
// XLO: read X lo plane. WRITELO: write C lo plane.
// FINAL: also write r*I - r^2*C to outp (fp32). MINC: min CTAs/SM. KC: k-chunk.
template<int SPLIT, int MODE, int XLO, int WRITELO, int FINAL, int NT, int MINC, int KC>
__global__ __launch_bounds__(256, MINC)
void gemm_mma(int sA, int sB, int sX, int sC, float* outp) {
    int z = blockIdx.z;
    if (!g_upd[z]) return;

    const int bim[12] = {0, 0, 0, 0, 0, 0, 1, 1, 1, 1, 2, 2};
    const int bjm[12] = {0, 1, 2, 3, 4, 5, 2, 3, 4, 5, 4, 5};
    int bi = bim[blockIdx.x], bj = bjm[blockIdx.x];
    int m0 = bi * 128, n0 = bj * NT;
    bool offd = ((bj >> 1) != bi);

    constexpr int LDTc = KC + 8;
    constexpr int PA_Ec = 128 * LDTc;
    constexpr int PA_Bc = PA_Ec * 2;
    constexpr int PB_Ec = NT * LDTc;
    constexpr int PB_Bc = PB_Ec * 2;
    constexpr int MT = 2;              // NT = 64
    constexpr int LDCn = 65;
    constexpr int STAGE_E = (SPLIT ? 2 : 1) * (PA_Ec + PB_Ec);
    constexpr uint32_t STAGE_B = STAGE_E * 2;
    constexpr int NCH = 384 / KC;

    size_t zo = (size_t)z * DP2;
    const __nv_bfloat16* AH = selH(sA) + zo;
    const __nv_bfloat16* AL = selL(sA) + zo;
    const __nv_bfloat16* BH = selH(sB) + zo;
    const __nv_bfloat16* BL = selL(sB) + zo;
    const __nv_bfloat16* XH = selH(sX) + zo;
    const __nv_bfloat16* XL = selL(sX) + zo;
    __nv_bfloat16* CH = selH(sC) + zo;
    __nv_bfloat16* CL = selL(sC) + zo;

    extern __shared__ __align__(16) __nv_bfloat16 sm[];
    float* Cs = reinterpret_cast<float*>(sm);
    uint32_t sbase = smem_u32(sm);

    int tid = threadIdx.x, wid = tid >> 5, lane = tid & 31;
    int wm = (wid & 3) * 32;
    int wn = (wid >> 2) * 32;

    float acc[MT][4][4];
    #pragma unroll
    for (int i = 0; i < MT; i++)
        #pragma unroll
        for (int j = 0; j < 4; j++)
            #pragma unroll
            for (int q = 0; q < 4; q++) acc[i][j][q] = 0.0f;

    int lt = lane >> 3, lr = lane & 7;
    int a_row = (lt & 1) * 8 + lr;
    int a_col = (lt >> 1) * 8;
    int b_row = (lt >> 1) * 8 + lr;
    int b_col = (lt & 1) * 8;

    auto do_stage = [&](int kc, int b) {
        uint32_t base = sbase + (uint32_t)b * STAGE_B;
        int k0 = kc * KC;
        stageP<128, KC>(AH, m0, k0, base, tid);
        stageP<NT, KC>(BH, n0, k0, base + PA_Bc, tid);
        if (SPLIT) {
            stageP<128, KC>(AL, m0, k0, base + PA_Bc + PB_Bc, tid);
            stageP<NT, KC>(BL, n0, k0, base + 2 * PA_Bc + PB_Bc, tid);
        }
        asm volatile("cp.async.commit_group;");
    };

    auto do_compute = [&](int cur) {
        const __nv_bfloat16* At  = sm + (size_t)cur * STAGE_E;
        const __nv_bfloat16* Bt  = At + PA_Ec;
        const __nv_bfloat16* Alt = Bt + PB_Ec;
        const __nv_bfloat16* Blt = Alt + PA_Ec;

        #pragma unroll
        for (int ks = 0; ks < KC / 16; ks++) {
            int kk = ks * 16;
            uint32_t ah[MT][4], bh[4][2];
            #pragma unroll
            for (int mt = 0; mt < MT; mt++)
                ldm_x4(ah[mt], smem_u32(&At[(wm + mt * 16 + a_row) * LDTc + kk + a_col]));
            #pragma unroll
            for (int np = 0; np < 2; np++) {
                uint32_t r[4];
                ldm_x4(r, smem_u32(&Bt[(wn + np * 16 + b_row) * LDTc + kk + b_col]));
                bh[np * 2][0] = r[0]; bh[np * 2][1] = r[1];
                bh[np * 2 + 1][0] = r[2]; bh[np * 2 + 1][1] = r[3];
            }
            #pragma unroll
            for (int mt = 0; mt < MT; mt++)
                #pragma unroll
                for (int nt = 0; nt < 4; nt++)
                    mma_bf16(acc[mt][nt], ah[mt], bh[nt]);

            if (SPLIT) {
                uint32_t bl[4][2];
                #pragma unroll
                for (int np = 0; np < 2; np++) {
                    uint32_t r[4];
                    ldm_x4(r, smem_u32(&Blt[(wn + np * 16 + b_row) * LDTc + kk + b_col]));
                    bl[np * 2][0] = r[0]; bl[np * 2][1] = r[1];
                    bl[np * 2 + 1][0] = r[2]; bl[np * 2 + 1][1] = r[3];
                }
                #pragma unroll
                for (int mt = 0; mt < MT; mt++)
                    #pragma unroll
                    for (int nt = 0; nt < 4; nt++)
                        mma_bf16(acc[mt][nt], ah[mt], bl[nt]);
                uint32_t al[MT][4];
                #pragma unroll
                for (int mt = 0; mt < MT; mt++)
                    ldm_x4(al[mt], smem_u32(&Alt[(wm + mt * 16 + a_row) * LDTc + kk + a_col]));
                #pragma unroll
                for (int mt = 0; mt < MT; mt++)
                    #pragma unroll
                    for (int nt = 0; nt < 4; nt++)
                        mma_bf16(acc[mt][nt], al[mt], bh[nt]);
            }
        }
    };

    do_stage(0, 0);
    for (int kc = 0; kc < NCH; kc++) {
        asm volatile("cp.async.wait_group 0;");
        __syncthreads();   // certifies compute(kc-1) done; buffer kc+1 free
        if (kc + 1 < NCH) do_stage(kc + 1, (kc + 1) & 1);
        do_compute(kc & 1);
    }
    __syncthreads();   // protect Cs reuse of staging smem

    // ---- epilogue ----
    float r = g_r[z];
    float rr = -r * r;
    #pragma unroll
    for (int mt = 0; mt < MT; mt++) {
        int rl0 = wm + mt * 16 + (lane >> 2);
        #pragma unroll
        for (int nt = 0; nt < 4; nt++) {
            int cl0 = wn + nt * 8 + 2 * (lane & 3);
            float v00 = acc[mt][nt][0], v01 = acc[mt][nt][1];
            float v10 = acc[mt][nt][2], v11 = acc[mt][nt][3];
            size_t g0 = (size_t)(m0 + rl0) * DP + n0 + cl0;
            size_t g1 = g0 + 8 * DP;
            int gi0 = m0 + rl0, gj = n0 + cl0;
            if (MODE == 1 || MODE == 6) {
                float2 xh0 = bf2f(*(const uint32_t*)(XH + g0));
                float2 xh1 = bf2f(*(const uint32_t*)(XH + g1));
                float x00 = xh0.x, x01 = xh0.y, x10 = xh1.x, x11 = xh1.y;
                if (XLO) {
                    float2 xl0 = bf2f(*(const uint32_t*)(XL + g0));
                    float2 xl1 = bf2f(*(const uint32_t*)(XL + g1));
                    x00 += xl0.x; x01 += xl0.y; x10 += xl1.x; x11 += xl1.y;
                }
                if (MODE == 1) {
                    v00 = 2.0f * x00 - v00; v01 = 2.0f * x01 - v01;
                    v10 = 2.0f * x10 - v10; v11 = 2.0f * x11 - v11;
                } else {                 // MODE 6: C = X - A*B
                    v00 = x00 - v00; v01 = x01 - v01;
                    v10 = x10 - v10; v11 = x11 - v11;
                }
            }
            if (MODE == 3) {   // C = A*B - I
                if (gi0 == gj)     v00 -= 1.0f;
                if (gi0 == gj + 1) v01 -= 1.0f;
                if (gi0 + 8 == gj)     v10 -= 1.0f;
                if (gi0 + 8 == gj + 1) v11 -= 1.0f;
            }
            uint32_t h, l;
            split2(v00, v01, h, l);
            *(uint32_t*)(CH + g0) = h;
            if (WRITELO) *(uint32_t*)(CL + g0) = l;
            split2(v10, v11, h, l);
            *(uint32_t*)(CH + g1) = h;
            if (WRITELO) *(uint32_t*)(CL + g1) = l;
            if (FINAL) {
                if (gj < DIN) {
                    if (gi0 < DIN) {
                        float2 o;
                        o.x = rr * v00 + ((gi0 == gj) ? r : 0.0f);
                        o.y = rr * v01 + ((gi0 == gj + 1) ? r : 0.0f);
                        *(float2*)(outp + (size_t)z * DD + (size_t)gi0 * DIN + gj) = o;
                    }
                    int gi1 = gi0 + 8;
                    if (gi1 < DIN) {
                        float2 o;
                        o.x = rr * v10 + ((gi1 == gj) ? r : 0.0f);
                        o.y = rr * v11 + ((gi1 == gj + 1) ? r : 0.0f);
                        *(float2*)(outp + (size_t)z * DD + (size_t)gi1 * DIN + gj) = o;
                    }
                }
            }
            if (offd) {
                Cs[rl0 * LDCn + cl0] = v00;
                Cs[rl0 * LDCn + cl0 + 1] = v01;
                Cs[(rl0 + 8) * LDCn + cl0] = v10;
                Cs[(rl0 + 8) * LDCn + cl0 + 1] = v11;
            }
        }
    }

    if (offd) {
        __syncthreads();
        #pragma unroll
        for (int it = 0; it < NT / 4; it++) {
            int p = it * 256 + tid;
            int cc = p >> 6, mp = (p & 63) * 2;
            float v0 = Cs[mp * LDCn + cc];
            float v1 = Cs[(mp + 1) * LDCn + cc];
            int gi = n0 + cc, gj = m0 + mp;
            size_t g = (size_t)gi * DP + gj;
            uint32_t h, l;
            split2(v0, v1, h, l);
            *(uint32_t*)(CH + g) = h;
            if (WRITELO) *(uint32_t*)(CL + g) = l;
            if (FINAL) {
                if (gi < DIN && gj < DIN) {
                    float2 o;
                    o.x = rr * v0;
                    o.y = rr * v1;
                    *(float2*)(outp + (size_t)z * DD + (size_t)gi * DIN + gj) = o;
                }
            }
        }
    }
}

// ---------------- mean output ----------------
__global__ void finalize_mean(const float* __restrict__ mean_in,
                              const float* __restrict__ obs,
                              float* __restrict__ out, int sinv) {
    int a = blockIdx.x;
    int tid = threadIdx.x;
    __shared__ float v[DIN];

    if (tid == 0) out[OUT_INIT + a] = g_initout[a] ? 1.0f : 0.0f;

    const float* m = mean_in + (size_t)a * DIN;
    const float* o = obs + (size_t)a * DIN;
    float* om = out + OUT_MEAN + (size_t)a * DIN;

    if (g_initnew[a]) {
        for (int i = tid; i < DIN; i += blockDim.x) om[i] = o[i];
    } else if (g_upd[a]) {
        float r = g_r[a];
        const __nv_bfloat16* Xh = selH(sinv) + (size_t)a * DP2;
        const __nv_bfloat16* Xl = selL(sinv) + (size_t)a * DP2;
        for (int j = tid; j < DIN; j += blockDim.x) v[j] = o[j] - m[srcIdx(j)];
        __syncthreads();
        int warp = tid >> 5, lane = tid & 31;
        for (int i = warp; i < DIN; i += 8) {
            float s = 0.0f;
            size_t row = (size_t)i * DP;
            for (int j = lane; j < DIN; j += 32)
                s += (__bfloat162float(Xh[row + j]) + __bfloat162float(Xl[row + j])) * v[j];
            #pragma unroll
            for (int off = 16; off; off >>= 1) s += __shfl_xor_sync(0xffffffffu, s, off);
            if (lane == 0) om[i] = o[i] - r * s;
        }
    } else {
        for (int i = tid; i < DIN; i += blockDim.x) om[i] = m[i];
    }
}

// ---------------- launch ----------------
extern "C" void kernel_launch(void* const* d_in, const int* in_sizes, int n_in,
                              void* d_out, int out_size) {
    const float* mean = (const float*)d_in[0];
    const float* cov  = (const float*)d_in[1];
    const float* obs  = (const float*)d_in[2];
    const float* rs   = (const float*)d_in[3];
    const void*  ini  = d_in[4];
    const void*  sel  = d_in[5];
    float* out = (float*)d_out;

    // plain KC=64: 2 stages x (128+64)*72*2 = 55296 B -> 3 CTAs/SM
    // split KC=32: 2 stages x 2 x (128+64)*40*2 = 61440 B -> 3 CTAs/SM
    const int SMB_P = 55296;
    const int SMB_S = 61440;

    cudaFuncSetAttribute(gemm_mma<0,0,0,0,0,64,3,64>, cudaFuncAttributeMaxDynamicSharedMemorySize, SMB_P);
    cudaFuncSetAttribute(gemm_mma<0,1,0,0,0,64,3,64>, cudaFuncAttributeMaxDynamicSharedMemorySize, SMB_P);
    cudaFuncSetAttribute(gemm_mma<0,1,0,1,0,64,3,64>, cudaFuncAttributeMaxDynamicSharedMemorySize, SMB_P);
    cudaFuncSetAttribute(gemm_mma<1,3,0,0,0,64,3,32>, cudaFuncAttributeMaxDynamicSharedMemorySize, SMB_S);
    cudaFuncSetAttribute(gemm_mma<0,6,1,1,1,64,3,64>, cudaFuncAttributeMaxDynamicSharedMemorySize, SMB_P);

    prep_flags<<<1, 64>>>(rs, ini, sel);
    build_S<<<dim3(DP / 8, NAG), 256>>>(cov, out);
    fill_X<<<dim3(144, NAG), 256>>>();

    dim3 g12(12, 1, NAG);
    // buffers: 0=S, 1=XA, 2=XB, 3=Y/D
    // plain Newton iter 1
    gemm_mma<0,0,0,0,0,64,3,64><<<g12, 256, SMB_P>>>(0, 1, 0, 3, nullptr);  // Y  = S*XA       (hi)
    gemm_mma<0,1,0,0,0,64,3,64><<<g12, 256, SMB_P>>>(1, 3, 1, 2, nullptr);  // XB = 2XA - XA*Y (hi)
    // plain Newton iter 2
    gemm_mma<0,0,0,0,0,64,3,64><<<g12, 256, SMB_P>>>(0, 2, 0, 3, nullptr);  // Y  = S*XB       (hi)
    gemm_mma<0,1,0,1,0,64,3,64><<<g12, 256, SMB_P>>>(2, 3, 2, 1, nullptr);  // XA = 2XB - XB*Y (hi+lo)
    // quadratic finish: Xf = XA - XA*D, D = S*XA - I (split, k32 double-buffered)
    gemm_mma<1,3,0,0,0,64,3,32><<<g12, 256, SMB_S>>>(0, 1, 0, 3, nullptr);  // D  = S*XA - I   (split, hi)
    gemm_mma<0,6,1,1,1,64,3,64><<<g12, 256, SMB_P>>>(1, 3, 1, 2, out + OUT_COV); // Xf = XA - XA*D (+cov)

    finalize_mean<<<NAG, 256>>>(mean, obs, out, 2);
}